// round 9
// baseline (speedup 1.0000x reference)
#include <cuda_runtime.h>
#include <math.h>
#include <stdint.h>

// ---------------- problem constants ----------------
#define NL   4
#define NB   64
#define NQ   4
#define NS   512
#define PSZ  16
#define NP   32
#define DM   2048
#define NH   32
#define NKV  8
#define HD   64
#define DFF  4096
#define NV   32000
#define NPAGES (NB*NP)
#define NT   (NB*NQ)      // 256 tokens
#define REPS 1e-5f

#define NQKV 3072         // 2048 q | 512 k | 512 v
#define NGU  8192         // 4096 gate | 4096 up

// ---------------- scratch ----------------
__device__ float g_hidden[NT*DM];
__device__ float g_hnorm [NT*DM];
__device__ float g_qkv   [NT*NQKV];
__device__ float g_attn  [NT*NH*HD];
__device__ float g_gu    [NT*NGU];
__device__ float g_part  [8ull*NT*NQKV];   // split-K partials (25 MB)

// ---------------- embedding gather ----------------
__global__ void embed_kernel(const float* __restrict__ embed,
                             const int* __restrict__ ids,
                             float* __restrict__ out) {
    int t = blockIdx.x;
    int id = ids[t];
    const float4* src = (const float4*)(embed + (size_t)id * DM);
    float4* dst = (float4*)(out + (size_t)t * DM);
    for (int i = threadIdx.x; i < DM/4; i += blockDim.x) dst[i] = src[i];
}

// ---------------- rmsnorm ----------------
__global__ void __launch_bounds__(256) rmsnorm_kernel(const float* __restrict__ x,
                                                      const float* __restrict__ w,
                                                      float* __restrict__ y) {
    int t = blockIdx.x;
    const float* xr = x + (size_t)t * DM;
    float ss = 0.f;
    for (int i = threadIdx.x; i < DM; i += 256) { float v = xr[i]; ss += v * v; }
    __shared__ float red[8];
    for (int o = 16; o; o >>= 1) ss += __shfl_xor_sync(~0u, ss, o);
    if ((threadIdx.x & 31) == 0) red[threadIdx.x >> 5] = ss;
    __syncthreads();
    if (threadIdx.x < 8) {
        float v = red[threadIdx.x];
        for (int o = 4; o; o >>= 1) v += __shfl_xor_sync(0xff, v, o);
        if (threadIdx.x == 0) red[0] = v;
    }
    __syncthreads();
    float inv = rsqrtf(red[0] / (float)DM + REPS);
    for (int i = threadIdx.x; i < DM; i += 256)
        y[(size_t)t * DM + i] = xr[i] * inv * w[i];
}

// ---------------- bf16 split helpers ----------------
__device__ __forceinline__ uint32_t cvt_bf2(float hi, float lo) {
    uint32_t r;
    asm("cvt.rn.bf16x2.f32 %0, %1, %2;" : "=r"(r) : "f"(hi), "f"(lo));
    return r;
}
__device__ __forceinline__ void ldsm4(uint32_t* r, uint32_t addr) {
    asm volatile("ldmatrix.sync.aligned.m8n8.x4.shared.b16 {%0,%1,%2,%3}, [%4];"
                 : "=r"(r[0]), "=r"(r[1]), "=r"(r[2]), "=r"(r[3]) : "r"(addr));
}
__device__ __forceinline__ void mma16816(float* c, const uint32_t* a,
                                         uint32_t b0, uint32_t b1) {
    asm volatile(
        "mma.sync.aligned.m16n8k16.row.col.f32.bf16.bf16.f32 "
        "{%0,%1,%2,%3},{%4,%5,%6,%7},{%8,%9},{%0,%1,%2,%3};"
        : "+f"(c[0]), "+f"(c[1]), "+f"(c[2]), "+f"(c[3])
        : "r"(a[0]), "r"(a[1]), "r"(a[2]), "r"(a[3]), "r"(b0), "r"(b1));
}

// ---------------- GEMM body: 256x64 tile (full M), BK=16, single-buffered ----
// A pre-offset to k0 (row-major, lda). B pre-offset to k0 row + n0 col (ldb).
// C pre-offset to n0 col (ldc). Res same or null. klen % 16 == 0.
__device__ __forceinline__ void gemm_body(
    const float* __restrict__ A, int lda,
    const float* __restrict__ B, int ldb,
    float* __restrict__ C, int ldc, const float* __restrict__ Res,
    int klen)
{
    __shared__ __align__(16) uint32_t AsU[2][256][12];   // [hi/lo][row][kword] 24.6KB
    __shared__ __align__(16) uint32_t BsU[2][64][12];    // 6.1KB

    int tid  = threadIdx.x;
    int lane = tid & 31;
    int warp = tid >> 5;
    int wm = warp >> 1, wn = warp & 1;

    int nB  = tid >> 2;            // B col (0..63)
    int ksw = (tid & 3) * 2;       // B word offset within BK (element k = ksw*2)

    const float* aptr = A + (size_t)tid * lda;   // one A row per thread
    const float* bptr = B + nB;
    int nk = klen >> 4;

    float acc[4][4][4];
#pragma unroll
    for (int i = 0; i < 4; i++)
#pragma unroll
        for (int j = 0; j < 4; j++)
#pragma unroll
            for (int k = 0; k < 4; k++) acc[i][j][k] = 0.f;

    // prefetch tile 0 into regs
    float4 pa[4]; float pb[4];
#pragma unroll
    for (int j = 0; j < 4; j++) pa[j] = *(const float4*)(aptr + j*4);
#pragma unroll
    for (int i = 0; i < 4; i++) pb[i] = bptr[(size_t)(ksw*2 + i) * ldb];

    // ldmatrix addressing
    uint32_t as_base = (uint32_t)__cvta_generic_to_shared(&AsU[0][0][0]);
    uint32_t bs_base = (uint32_t)__cvta_generic_to_shared(&BsU[0][0][0]);
    int a_ro = ((lane >> 3) & 1) * 8 + (lane & 7);
    int a_ch = (lane >> 4) * 8;
    int b_ro = ((lane >> 4) & 1) * 8 + (lane & 7);
    int b_ch = ((lane >> 3) & 1) * 8;

    uint32_t aaddr[2][4], baddr[2][2];   // [hi/lo][tile]
#pragma unroll
    for (int b = 0; b < 2; b++) {
#pragma unroll
        for (int mt = 0; mt < 4; mt++)
            aaddr[b][mt] = as_base + (uint32_t)b * 12288u
                         + ((wm*64 + mt*16 + a_ro) * 12) * 4 + a_ch * 2;
#pragma unroll
        for (int nt2 = 0; nt2 < 2; nt2++)
            baddr[b][nt2] = bs_base + (uint32_t)b * 3072u
                          + ((wn*32 + nt2*16 + b_ro) * 12) * 4 + b_ch * 2;
    }

    for (int kt = 0; kt < nk; kt++) {
        __syncthreads();   // previous tile fully consumed

        // ---- convert & store tile kt (regs -> smem) ----
        {
            const float* xs = (const float*)pa;
            uint32_t hiw[8], low[8];
#pragma unroll
            for (int j = 0; j < 8; j++) {
                uint32_t h = cvt_bf2(xs[2*j+1], xs[2*j]);
                float f0 = __uint_as_float(h << 16);
                float f1 = __uint_as_float(h & 0xffff0000u);
                hiw[j] = h;
                low[j] = cvt_bf2(xs[2*j+1] - f1, xs[2*j] - f0);
            }
            uint4* ah = (uint4*)&AsU[0][tid][0];
            ah[0] = make_uint4(hiw[0], hiw[1], hiw[2], hiw[3]);
            ah[1] = make_uint4(hiw[4], hiw[5], hiw[6], hiw[7]);
            uint4* al = (uint4*)&AsU[1][tid][0];
            al[0] = make_uint4(low[0], low[1], low[2], low[3]);
            al[1] = make_uint4(low[4], low[5], low[6], low[7]);

            uint32_t h0 = cvt_bf2(pb[1], pb[0]);
            uint32_t h1 = cvt_bf2(pb[3], pb[2]);
            float g0 = __uint_as_float(h0 << 16);
            float g1 = __uint_as_float(h0 & 0xffff0000u);
            float g2 = __uint_as_float(h1 << 16);
            float g3 = __uint_as_float(h1 & 0xffff0000u);
            BsU[0][nB][ksw]     = h0;
            BsU[0][nB][ksw + 1] = h1;
            BsU[1][nB][ksw]     = cvt_bf2(pb[1] - g1, pb[0] - g0);
            BsU[1][nB][ksw + 1] = cvt_bf2(pb[3] - g3, pb[2] - g2);
        }
        __syncthreads();   // tile kt visible

        // ---- prefetch tile kt+1 (latency hides under mma below) ----
        if (kt + 1 < nk) {
            aptr += 16;
#pragma unroll
            for (int j = 0; j < 4; j++) pa[j] = *(const float4*)(aptr + j*4);
            size_t kb = (size_t)((kt + 1) * 16 + ksw * 2);
#pragma unroll
            for (int i = 0; i < 4; i++) pb[i] = bptr[(kb + i) * ldb];
        }

        // ---- 3-pass mma ----
        uint32_t Ah[4][4], Bh[2][4];
#pragma unroll
        for (int mt = 0; mt < 4; mt++) ldsm4(Ah[mt], aaddr[0][mt]);
        ldsm4(Bh[0], baddr[0][0]); ldsm4(Bh[1], baddr[0][1]);
#pragma unroll
        for (int mt = 0; mt < 4; mt++)
#pragma unroll
            for (int nt = 0; nt < 4; nt++)
                mma16816(acc[mt][nt], Ah[mt], Bh[nt>>1][(nt&1)*2], Bh[nt>>1][(nt&1)*2+1]);

        {
            uint32_t Bl[2][4];
            ldsm4(Bl[0], baddr[1][0]); ldsm4(Bl[1], baddr[1][1]);
#pragma unroll
            for (int mt = 0; mt < 4; mt++)
#pragma unroll
                for (int nt = 0; nt < 4; nt++)
                    mma16816(acc[mt][nt], Ah[mt], Bl[nt>>1][(nt&1)*2], Bl[nt>>1][(nt&1)*2+1]);
        }
        {
            uint32_t Al[4][4];
#pragma unroll
            for (int mt = 0; mt < 4; mt++) ldsm4(Al[mt], aaddr[1][mt]);
#pragma unroll
            for (int mt = 0; mt < 4; mt++)
#pragma unroll
                for (int nt = 0; nt < 4; nt++)
                    mma16816(acc[mt][nt], Al[mt], Bh[nt>>1][(nt&1)*2], Bh[nt>>1][(nt&1)*2+1]);
        }
    }

    // ---- epilogue ----
    int g = lane >> 2, t4 = lane & 3;
#pragma unroll
    for (int mt = 0; mt < 4; mt++) {
#pragma unroll
        for (int nt = 0; nt < 4; nt++) {
            int row = wm*64 + mt*16 + g;
            int col = wn*32 + nt*8 + t4*2;
            float* cp0 = C + (size_t)row * ldc + col;
            float* cp1 = cp0 + (size_t)8 * ldc;
            float2 v0 = make_float2(acc[mt][nt][0], acc[mt][nt][1]);
            float2 v1 = make_float2(acc[mt][nt][2], acc[mt][nt][3]);
            if (Res) {
                const float* r0 = Res + (size_t)row * ldc + col;
                const float* r1 = r0 + (size_t)8 * ldc;
                v0.x += r0[0]; v0.y += r0[1];
                v1.x += r1[0]; v1.y += r1[1];
            }
            *(float2*)cp0 = v0;
            *(float2*)cp1 = v1;
        }
    }
}

// ---------------- GEMM wrappers ----------------
// generic: grid (N/64, 1, S). If S>1 writes fp32 partials into C (partial buf).
__global__ void __launch_bounds__(256) gemm_k(const float* __restrict__ A, int lda,
                                              const float* __restrict__ B,
                                              float* __restrict__ C,
                                              const float* __restrict__ Res,
                                              int N, int klen) {
    int s = blockIdx.z;
    int n0 = blockIdx.x * 64;
    const float* Ao = A + (size_t)s * klen;
    const float* Bo = B + (size_t)s * klen * N + n0;
    float* Cout; const float* R;
    if (gridDim.z == 1) { Cout = C + n0; R = Res ? Res + n0 : nullptr; }
    else { Cout = C + (size_t)s * NT * N + n0; R = nullptr; }
    gemm_body(Ao, lda, Bo, N, Cout, N, R, klen);
}

// fused qkv: grid (48, 1, 8), klen=256, partial [s][NT][3072]
__global__ void __launch_bounds__(256) gemm_qkv(const float* __restrict__ A,
                                                const float* __restrict__ Bq,
                                                const float* __restrict__ Bk,
                                                const float* __restrict__ Bv,
                                                float* __restrict__ part) {
    int bx = blockIdx.x, s = blockIdx.z;
    const float* B; int ldb, nloc;
    if (bx < 32)      { B = Bq; ldb = 2048; nloc = bx * 64; }
    else if (bx < 40) { B = Bk; ldb = 512;  nloc = (bx - 32) * 64; }
    else              { B = Bv; ldb = 512;  nloc = (bx - 40) * 64; }
    const float* Ao = A + (size_t)s * 256;
    const float* Bo = B + (size_t)s * 256 * ldb + nloc;
    float* Cout = part + (size_t)s * NT * NQKV + bx * 64;
    gemm_body(Ao, DM, Bo, ldb, Cout, NQKV, nullptr, 256);
}

// fused gate|up: grid (128, 1, 1), DIRECT write into gu, klen=2048
__global__ void __launch_bounds__(256) gemm_gu(const float* __restrict__ A,
                                               const float* __restrict__ Bg,
                                               const float* __restrict__ Bu,
                                               float* __restrict__ gu) {
    int bx = blockIdx.x;
    const float* Bo; float* Cout;
    if (bx < 64) { Bo = Bg + bx * 64;        Cout = gu + bx * 64; }
    else         { Bo = Bu + (bx - 64) * 64; Cout = gu + DFF + (bx - 64) * 64; }
    gemm_body(A, DM, Bo, DFF, Cout, NGU, nullptr, 2048);
}

// ---------------- split-K reduce (+ optional residual) ----------------
__global__ void __launch_bounds__(256) reduce_kernel(float* __restrict__ dst,
                                                     const float* __restrict__ part,
                                                     const float* __restrict__ Res,
                                                     int total, int S) {
    int i = (blockIdx.x * 256 + threadIdx.x) * 4;
    if (i >= total) return;
    float4 v = Res ? *(const float4*)(Res + i) : make_float4(0.f, 0.f, 0.f, 0.f);
    for (int s = 0; s < S; s++) {
        float4 p = *(const float4*)(part + (size_t)s * total + i);
        v.x += p.x; v.y += p.y; v.z += p.z; v.w += p.w;
    }
    *(float4*)(dst + i) = v;
}

// ---------------- RoPE on fused qkv buffer ----------------
__global__ void rope_kernel(float* __restrict__ qkv) {
    int idx = blockIdx.x * blockDim.x + threadIdx.x;
    const int NQE = NT * NH  * 32;
    const int NKE = NT * NKV * 32;
    float* base; int d, pos;
    if (idx < NQE) {
        d = idx & 31;
        int h = (idx >> 5) % NH;
        int t = idx / (32 * NH);
        pos = NS + (t % NQ);
        base = qkv + (size_t)t * NQKV + h * HD;
    } else if (idx < NQE + NKE) {
        int j = idx - NQE;
        d = j & 31;
        int h = (j >> 5) % NKV;
        int t = j / (32 * NKV);
        pos = NS + (t % NQ);
        base = qkv + (size_t)t * NQKV + 2048 + h * HD;
    } else return;
    float inv = powf(10000.0f, -(float)d * (1.0f / 32.0f));
    float ang = (float)pos * inv;
    float c = cosf(ang), s = sinf(ang);
    float x1 = base[d], x2 = base[d + 32];
    base[d]      = x1 * c - x2 * s;
    base[d + 32] = x2 * c + x1 * s;
}

// ---------------- fused paged attention ----------------
__global__ void __launch_bounds__(256) attn_kernel(
    const float* __restrict__ kc, const float* __restrict__ vc,
    const int* __restrict__ page_table, const int* __restrict__ req_id,
    const float* __restrict__ qkv, float* __restrict__ aout) {

    __shared__ float q_s[16 * 64];
    __shared__ float sc [16 * 520];
    __shared__ float tile[64 * 33];
    __shared__ float rowinv[16];
    __shared__ int pages[NP];

    int kvh = blockIdx.x, b = blockIdx.y;
    int tid = threadIdx.x;

    if (tid < NP) pages[tid] = page_table[req_id[b] * NP + tid];
    {
        int row = tid >> 4;
        int d0  = (tid & 15) * 4;
        int hp = row >> 2, qi = row & 3;
        float4 v = *(const float4*)(qkv + (size_t)(b*NQ + qi) * NQKV + (kvh*4 + hp) * HD + d0);
        *(float4*)(q_s + row * 64 + d0) = v;
    }
    __syncthreads();

    const float scale = 0.125f;
    int jj_l = tid >> 3;
    int f4i  = tid & 7;
    int jj_c = tid & 31;
    int rgrp = tid >> 5;

    for (int t0 = 0; t0 < 16; t0++) {
        int j = t0 * 32 + jj_l;
        int page = pages[j >> 4];
        const float* kr = kc + (((size_t)page * PSZ + (j & 15)) * NKV + kvh) * HD;
#pragma unroll
        for (int i = 0; i < 2; i++) {
            int d0 = (f4i + 8 * i) * 4;
            float4 v = *(const float4*)(kr + d0);
            tile[(d0+0)*33 + jj_l] = v.x;
            tile[(d0+1)*33 + jj_l] = v.y;
            tile[(d0+2)*33 + jj_l] = v.z;
            tile[(d0+3)*33 + jj_l] = v.w;
        }
        __syncthreads();
        float a0 = 0.f, a1 = 0.f;
        const float* q0 = q_s + rgrp * 64;
        const float* q1 = q_s + (rgrp + 8) * 64;
#pragma unroll
        for (int d = 0; d < 64; d++) {
            float kv = tile[d * 33 + jj_c];
            a0 += kv * q0[d];
            a1 += kv * q1[d];
        }
        sc[rgrp       * 520 + t0*32 + jj_c] = a0 * scale;
        sc[(rgrp + 8) * 520 + t0*32 + jj_c] = a1 * scale;
        __syncthreads();
    }
    if (tid < 64) {
        int hp = tid >> 4, qi = (tid >> 2) & 3, qj = tid & 3;
        int row = hp * 4 + qi;
        const float* kr = qkv + (size_t)(b*NQ + qj) * NQKV + 2048 + kvh * HD;
        const float* qr = q_s + row * 64;
        float a = 0.f;
#pragma unroll
        for (int d = 0; d < 64; d++) a += qr[d] * kr[d];
        sc[row * 520 + 512 + qj] = (qj <= qi) ? a * scale : -1e30f;
    }
    __syncthreads();

    {
        int w = tid >> 5, lane = tid & 31;
        for (int rr = 0; rr < 2; rr++) {
            int row = w * 2 + rr;
            float* srow = sc + row * 520;
            float m = -1e30f;
            for (int j = lane; j < 516; j += 32) m = fmaxf(m, srow[j]);
            for (int o = 16; o; o >>= 1) m = fmaxf(m, __shfl_xor_sync(~0u, m, o));
            float s = 0.f;
            for (int j = lane; j < 516; j += 32) {
                float p = expf(srow[j] - m);
                srow[j] = p;
                s += p;
            }
            for (int o = 16; o; o >>= 1) s += __shfl_xor_sync(~0u, s, o);
            if (lane == 0) rowinv[row] = 1.f / s;
        }
    }
    __syncthreads();

    int d = tid & 63, rbase = tid >> 6;
    float oacc[4] = {0.f, 0.f, 0.f, 0.f};
    for (int t0 = 0; t0 < 16; t0++) {
        int j = t0 * 32 + jj_l;
        int page = pages[j >> 4];
        const float* vr = vc + (((size_t)page * PSZ + (j & 15)) * NKV + kvh) * HD;
#pragma unroll
        for (int i = 0; i < 2; i++) {
            int d0 = (f4i + 8 * i) * 4;
            float4 v = *(const float4*)(vr + d0);
            tile[(d0+0)*33 + jj_l] = v.x;
            tile[(d0+1)*33 + jj_l] = v.y;
            tile[(d0+2)*33 + jj_l] = v.z;
            tile[(d0+3)*33 + jj_l] = v.w;
        }
        __syncthreads();
#pragma unroll
        for (int jj = 0; jj < 32; jj++) {
            float vv = tile[d * 33 + jj];
            int jc = t0 * 32 + jj;
            oacc[0] += sc[(rbase     ) * 520 + jc] * vv;
            oacc[1] += sc[(rbase +  4) * 520 + jc] * vv;
            oacc[2] += sc[(rbase +  8) * 520 + jc] * vv;
            oacc[3] += sc[(rbase + 12) * 520 + jc] * vv;
        }
        __syncthreads();
    }
#pragma unroll
    for (int qj = 0; qj < 4; qj++) {
        float vv = qkv[(size_t)(b*NQ + qj) * NQKV + 2560 + kvh * HD + d];
        oacc[0] += sc[(rbase     ) * 520 + 512 + qj] * vv;
        oacc[1] += sc[(rbase +  4) * 520 + 512 + qj] * vv;
        oacc[2] += sc[(rbase +  8) * 520 + 512 + qj] * vv;
        oacc[3] += sc[(rbase + 12) * 520 + 512 + qj] * vv;
    }
#pragma unroll
    for (int r = 0; r < 4; r++) {
        int row = rbase + r * 4;
        int hp = row >> 2, qi = row & 3;
        aout[((size_t)(b*NQ + qi) * NH + (kvh*4 + hp)) * HD + d] = oacc[r] * rowinv[row];
    }
}

// ---------------- silu(gate) * up (in-place into gate region of gu) --------
__global__ void silu_mul_kernel(float* __restrict__ gu) {
    int i = blockIdx.x * blockDim.x + threadIdx.x;
    if (i < NT * DFF) {
        int row = i / DFF, c = i % DFF;
        float x = gu[(size_t)row * NGU + c];
        float u = gu[(size_t)row * NGU + DFF + c];
        gu[(size_t)row * NGU + c] = (x / (1.f + expf(-x))) * u;
    }
}

// ---------------- host orchestration ----------------
extern "C" void kernel_launch(void* const* d_in, const int* in_sizes, int n_in,
                              void* d_out, int out_size) {
    const int*   input_ids  = (const int*)  d_in[0];
    const int*   req_id     = (const int*)  d_in[1];
    const int*   page_table = (const int*)  d_in[2];
    const float* embed      = (const float*)d_in[3];
    const float* w_in_ln    = (const float*)d_in[4];
    const float* wq         = (const float*)d_in[5];
    const float* wk         = (const float*)d_in[6];
    const float* wv         = (const float*)d_in[7];
    const float* wo         = (const float*)d_in[8];
    const float* w_post_ln  = (const float*)d_in[9];
    const float* w_gate     = (const float*)d_in[10];
    const float* w_up       = (const float*)d_in[11];
    const float* w_down     = (const float*)d_in[12];
    const float* k_cache    = (const float*)d_in[13];
    const float* v_cache    = (const float*)d_in[14];
    const float* lm_head    = (const float*)d_in[15];
    float* out = (float*)d_out;

    float *hid, *hn, *qkvb, *ao, *gu, *part;
    cudaGetSymbolAddress((void**)&hid,  g_hidden);
    cudaGetSymbolAddress((void**)&hn,   g_hnorm);
    cudaGetSymbolAddress((void**)&qkvb, g_qkv);
    cudaGetSymbolAddress((void**)&ao,   g_attn);
    cudaGetSymbolAddress((void**)&gu,   g_gu);
    cudaGetSymbolAddress((void**)&part, g_part);

    embed_kernel<<<NT, 256>>>(embed, input_ids, hid);

    for (int l = 0; l < NL; l++) {
        const float* wq_l = wq + (size_t)l * DM * (NH * HD);
        const float* wk_l = wk + (size_t)l * DM * (NKV * HD);
        const float* wv_l = wv + (size_t)l * DM * (NKV * HD);
        const float* wo_l = wo + (size_t)l * (NH * HD) * DM;
        const float* wg_l = w_gate + (size_t)l * DM * DFF;
        const float* wu_l = w_up   + (size_t)l * DM * DFF;
        const float* wd_l = w_down + (size_t)l * DFF * DM;
        const float* kc_l = k_cache + (size_t)l * NPAGES * PSZ * NKV * HD;
        const float* vc_l = v_cache + (size_t)l * NPAGES * PSZ * NKV * HD;

        rmsnorm_kernel<<<NT, 256>>>(hid, w_in_ln + (size_t)l * DM, hn);

        gemm_qkv<<<dim3(48, 1, 8), 256>>>(hn, wq_l, wk_l, wv_l, part);
        reduce_kernel<<<(NT*NQKV)/1024, 256>>>(qkvb, part, nullptr, NT*NQKV, 8);

        rope_kernel<<<(NT*NH*32 + NT*NKV*32) / 256, 256>>>(qkvb);
        attn_kernel<<<dim3(NKV, NB), 256>>>(kc_l, vc_l, page_table, req_id, qkvb, ao);

        gemm_k<<<dim3(32, 1, 4), 256>>>(ao, NH*HD, wo_l, part, nullptr, DM, 512);
        reduce_kernel<<<(NT*DM)/1024, 256>>>(hid, part, hid, NT*DM, 4);

        rmsnorm_kernel<<<NT, 256>>>(hid, w_post_ln + (size_t)l * DM, hn);

        gemm_gu<<<dim3(128, 1, 1), 256>>>(hn, wg_l, wu_l, gu);
        silu_mul_kernel<<<(NT * DFF + 255) / 256, 256>>>(gu);

        gemm_k<<<dim3(32, 1, 4), 256>>>(gu, NGU, wd_l, part, nullptr, DM, 1024);
        reduce_kernel<<<(NT*DM)/1024, 256>>>(hid, part, hid, NT*DM, 4);
    }

    gemm_k<<<dim3(NV/64, 1, 1), 256>>>(hid, DM, lm_head, out, nullptr, NV, 2048);
}

// round 11
// speedup vs baseline: 1.1851x; 1.1851x over previous
#include <cuda_runtime.h>
#include <cuda_fp16.h>
#include <math.h>
#include <stdint.h>

// ---------------- problem constants ----------------
#define NL   4
#define NB   64
#define NQ   4
#define NS   512
#define PSZ  16
#define NP   32
#define DM   2048
#define NH   32
#define NKV  8
#define HD   64
#define DFF  4096
#define NV   32000
#define NPAGES (NB*NP)
#define NT   (NB*NQ)      // 256 tokens
#define REPS 1e-5f

#define NQKV 3072         // 2048 q | 512 k | 512 v
#define NGU  8192         // 4096 gate | 4096 up

// ---------------- scratch ----------------
__device__ float g_hidden[NT*DM];
__device__ float g_hnorm [NT*DM];
__device__ float g_qkv   [NT*NQKV];
__device__ float g_attn  [NT*NH*HD];
__device__ float g_gu    [NT*NGU];
__device__ float g_part  [4ull*NT*NQKV];   // split-K partials

// ---------------- embedding gather ----------------
__global__ void embed_kernel(const float* __restrict__ embed,
                             const int* __restrict__ ids,
                             float* __restrict__ out) {
    int t = blockIdx.x;
    int id = ids[t];
    const float4* src = (const float4*)(embed + (size_t)id * DM);
    float4* dst = (float4*)(out + (size_t)t * DM);
    for (int i = threadIdx.x; i < DM/4; i += blockDim.x) dst[i] = src[i];
}

// ---------------- rmsnorm (used once, after embed) ----------------
__global__ void __launch_bounds__(256) rmsnorm_kernel(const float* __restrict__ x,
                                                      const float* __restrict__ w,
                                                      float* __restrict__ y) {
    int t = blockIdx.x;
    const float* xr = x + (size_t)t * DM;
    float ss = 0.f;
    for (int i = threadIdx.x; i < DM; i += 256) { float v = xr[i]; ss += v * v; }
    __shared__ float red[8];
    for (int o = 16; o; o >>= 1) ss += __shfl_xor_sync(~0u, ss, o);
    if ((threadIdx.x & 31) == 0) red[threadIdx.x >> 5] = ss;
    __syncthreads();
    if (threadIdx.x < 8) {
        float v = red[threadIdx.x];
        for (int o = 4; o; o >>= 1) v += __shfl_xor_sync(0xff, v, o);
        if (threadIdx.x == 0) red[0] = v;
    }
    __syncthreads();
    float inv = rsqrtf(red[0] / (float)DM + REPS);
    for (int i = threadIdx.x; i < DM; i += 256)
        y[(size_t)t * DM + i] = xr[i] * inv * w[i];
}

// ---------------- fp16 split helpers ----------------
__device__ __forceinline__ uint32_t h2bits(__half2 h) {
    return *reinterpret_cast<uint32_t*>(&h);
}
__device__ __forceinline__ void ldsm4(uint32_t* r, uint32_t addr) {
    asm volatile("ldmatrix.sync.aligned.m8n8.x4.shared.b16 {%0,%1,%2,%3}, [%4];"
                 : "=r"(r[0]), "=r"(r[1]), "=r"(r[2]), "=r"(r[3]) : "r"(addr));
}
__device__ __forceinline__ void mma16816(float* c, const uint32_t* a,
                                         uint32_t b0, uint32_t b1) {
    asm volatile(
        "mma.sync.aligned.m16n8k16.row.col.f32.f16.f16.f32 "
        "{%0,%1,%2,%3},{%4,%5,%6,%7},{%8,%9},{%0,%1,%2,%3};"
        : "+f"(c[0]), "+f"(c[1]), "+f"(c[2]), "+f"(c[3])
        : "r"(a[0]), "r"(a[1]), "r"(a[2]), "r"(a[3]), "r"(b0), "r"(b1));
}

// fp32 -> A: hi/lo fp16 split ; B: single fp16 round.  STS into one stage.
__device__ __forceinline__ void convert_store(
    uint32_t (*As)[128][12], uint32_t (*Bs)[12],
    const float4& pa0, const float4& pa1,
    float pb0, float pb1, float pb2, float pb3,
    int mA, int kqw, int nB, int ksw)
{
    float xs[8] = {pa0.x, pa0.y, pa0.z, pa0.w, pa1.x, pa1.y, pa1.z, pa1.w};
#pragma unroll
    for (int j = 0; j < 4; j++) {
        __half2 h = __floats2half2_rn(xs[2*j], xs[2*j+1]);
        float r0 = xs[2*j]   - __low2float(h);
        float r1 = xs[2*j+1] - __high2float(h);
        As[0][mA][kqw + j] = h2bits(h);
        As[1][mA][kqw + j] = h2bits(__floats2half2_rn(r0, r1));
    }
    Bs[nB][ksw]     = h2bits(__floats2half2_rn(pb0, pb1));
    Bs[nB][ksw + 1] = h2bits(__floats2half2_rn(pb2, pb3));
}

// ---------------- GEMM body: 128x64 tile, BK=16, double-buffered ------------
// 2-pass fp16: acc = Ah*Bf + Al*Bf  (A split hi/lo, B rounded once)
__device__ __forceinline__ void gemm_body(
    const float* __restrict__ A, int lda,
    const float* __restrict__ B, int ldb,
    float* __restrict__ C, int ldc, const float* __restrict__ Res,
    int m0, int klen)
{
    __shared__ uint32_t AsU[2][2][128][12];   // [stage][hi/lo][row][kword]
    __shared__ uint32_t BsU[2][64][12];       // [stage][col][kword] (single fp16)

    int tid  = threadIdx.x;
    int lane = tid & 31;
    int warp = tid >> 5;
    int wm = warp >> 1, wn = warp & 1;

    int mA  = tid >> 1;
    int kq8 = (tid & 1) * 8;
    int kqw = (tid & 1) * 4;
    int nB  = tid >> 2;
    int ksw = (tid & 3) * 2;

    const float* aptr = A + (size_t)(m0 + mA) * lda + kq8;
    const float* bptr = B + nB;
    int nk = klen >> 4;

    float acc[2][4][4];
#pragma unroll
    for (int i = 0; i < 2; i++)
#pragma unroll
        for (int j = 0; j < 4; j++)
#pragma unroll
            for (int k = 0; k < 4; k++) acc[i][j][k] = 0.f;

    // prologue: load tile 0, store stage 0, load tile 1
    float4 pa0 = *(const float4*)aptr;
    float4 pa1 = *(const float4*)(aptr + 4);
    float pb0 = bptr[(size_t)(ksw*2 + 0) * ldb];
    float pb1 = bptr[(size_t)(ksw*2 + 1) * ldb];
    float pb2 = bptr[(size_t)(ksw*2 + 2) * ldb];
    float pb3 = bptr[(size_t)(ksw*2 + 3) * ldb];
    convert_store(AsU[0], BsU[0], pa0, pa1, pb0, pb1, pb2, pb3, mA, kqw, nB, ksw);
    if (nk > 1) {
        aptr += 16;
        pa0 = *(const float4*)aptr;
        pa1 = *(const float4*)(aptr + 4);
        size_t kb = (size_t)(16 + ksw * 2);
        pb0 = bptr[(kb + 0) * ldb];
        pb1 = bptr[(kb + 1) * ldb];
        pb2 = bptr[(kb + 2) * ldb];
        pb3 = bptr[(kb + 3) * ldb];
    }
    __syncthreads();

    // ldmatrix addressing
    uint32_t as_base = (uint32_t)__cvta_generic_to_shared(&AsU[0][0][0][0]);
    uint32_t bs_base = (uint32_t)__cvta_generic_to_shared(&BsU[0][0][0]);
    int a_ro = ((lane >> 3) & 1) * 8 + (lane & 7);
    int a_ch = (lane >> 4) * 8;
    int b_ro = ((lane >> 4) & 1) * 8 + (lane & 7);
    int b_ch = ((lane >> 3) & 1) * 8;

    uint32_t aaddr[2][2], baddr[2];   // aaddr[hi/lo][mt], baddr[nt2]
#pragma unroll
    for (int b = 0; b < 2; b++)
#pragma unroll
        for (int mt = 0; mt < 2; mt++)
            aaddr[b][mt] = as_base + (uint32_t)b * 6144u
                         + ((wm*32 + mt*16 + a_ro) * 12) * 4 + a_ch * 2;
#pragma unroll
    for (int nt2 = 0; nt2 < 2; nt2++)
        baddr[nt2] = bs_base + ((wn*32 + nt2*16 + b_ro) * 12) * 4 + b_ch * 2;

    for (int kt = 0; kt < nk; kt++) {
        int st = kt & 1;
        if (kt + 1 < nk)
            convert_store(AsU[st ^ 1], BsU[st ^ 1], pa0, pa1, pb0, pb1, pb2, pb3,
                          mA, kqw, nB, ksw);
        if (kt + 2 < nk) {
            aptr += 16;
            pa0 = *(const float4*)aptr;
            pa1 = *(const float4*)(aptr + 4);
            size_t kb = (size_t)((kt + 2) * 16 + ksw * 2);
            pb0 = bptr[(kb + 0) * ldb];
            pb1 = bptr[(kb + 1) * ldb];
            pb2 = bptr[(kb + 2) * ldb];
            pb3 = bptr[(kb + 3) * ldb];
        }

        uint32_t aoff = (uint32_t)st * 12288u;
        uint32_t boff = (uint32_t)st * 3072u;
        uint32_t Ah[2][4], Al[2][4], Bf[2][4];
        ldsm4(Ah[0], aaddr[0][0] + aoff); ldsm4(Ah[1], aaddr[0][1] + aoff);
        ldsm4(Bf[0], baddr[0] + boff);    ldsm4(Bf[1], baddr[1] + boff);
#pragma unroll
        for (int mt = 0; mt < 2; mt++)
#pragma unroll
            for (int nt = 0; nt < 4; nt++)
                mma16816(acc[mt][nt], Ah[mt], Bf[nt>>1][(nt&1)*2], Bf[nt>>1][(nt&1)*2+1]);

        ldsm4(Al[0], aaddr[1][0] + aoff); ldsm4(Al[1], aaddr[1][1] + aoff);
#pragma unroll
        for (int mt = 0; mt < 2; mt++)
#pragma unroll
            for (int nt = 0; nt < 4; nt++)
                mma16816(acc[mt][nt], Al[mt], Bf[nt>>1][(nt&1)*2], Bf[nt>>1][(nt&1)*2+1]);

        __syncthreads();
    }

    // epilogue
    int g = lane >> 2, t4 = lane & 3;
#pragma unroll
    for (int mt = 0; mt < 2; mt++) {
#pragma unroll
        for (int nt = 0; nt < 4; nt++) {
            int row = m0 + wm*32 + mt*16 + g;
            int col = wn*32 + nt*8 + t4*2;
            float* cp0 = C + (size_t)row * ldc + col;
            float* cp1 = cp0 + (size_t)8 * ldc;
            float2 v0 = make_float2(acc[mt][nt][0], acc[mt][nt][1]);
            float2 v1 = make_float2(acc[mt][nt][2], acc[mt][nt][3]);
            if (Res) {
                const float* r0 = Res + (size_t)row * ldc + col;
                const float* r1 = r0 + (size_t)8 * ldc;
                v0.x += r0[0]; v0.y += r0[1];
                v1.x += r1[0]; v1.y += r1[1];
            }
            *(float2*)cp0 = v0;
            *(float2*)cp1 = v1;
        }
    }
}

// ---------------- GEMM wrappers ----------------
__global__ void __launch_bounds__(256) gemm_k(const float* __restrict__ A, int lda,
                                              const float* __restrict__ B,
                                              float* __restrict__ C,
                                              const float* __restrict__ Res,
                                              int N, int klen) {
    int s = blockIdx.z;
    int m0 = blockIdx.y * 128;
    int n0 = blockIdx.x * 64;
    const float* Ao = A + (size_t)s * klen;
    const float* Bo = B + (size_t)s * klen * N + n0;
    float* Cout; const float* R;
    if (gridDim.z == 1) { Cout = C + n0; R = Res ? Res + n0 : nullptr; }
    else { Cout = C + (size_t)s * NT * N + n0; R = nullptr; }
    gemm_body(Ao, lda, Bo, N, Cout, N, R, m0, klen);
}

// fused qkv: grid (48, 2, 4), klen=512, partial [s][NT][3072]
__global__ void __launch_bounds__(256) gemm_qkv(const float* __restrict__ A,
                                                const float* __restrict__ Bq,
                                                const float* __restrict__ Bk,
                                                const float* __restrict__ Bv,
                                                float* __restrict__ part) {
    int bx = blockIdx.x, s = blockIdx.z;
    int m0 = blockIdx.y * 128;
    const float* B; int ldb, nloc;
    if (bx < 32)      { B = Bq; ldb = 2048; nloc = bx * 64; }
    else if (bx < 40) { B = Bk; ldb = 512;  nloc = (bx - 32) * 64; }
    else              { B = Bv; ldb = 512;  nloc = (bx - 40) * 64; }
    const float* Ao = A + (size_t)s * 512;
    const float* Bo = B + (size_t)s * 512 * ldb + nloc;
    float* Cout = part + (size_t)s * NT * NQKV + bx * 64;
    gemm_body(Ao, DM, Bo, ldb, Cout, NQKV, nullptr, m0, 512);
}

// fused gate|up: grid (128, 2, 1), direct write into gu, klen=2048
__global__ void __launch_bounds__(256) gemm_gu(const float* __restrict__ A,
                                               const float* __restrict__ Bg,
                                               const float* __restrict__ Bu,
                                               float* __restrict__ gu) {
    int bx = blockIdx.x;
    int m0 = blockIdx.y * 128;
    const float* Bo; float* Cout;
    if (bx < 64) { Bo = Bg + bx * 64;        Cout = gu + bx * 64; }
    else         { Bo = Bu + (bx - 64) * 64; Cout = gu + DFF + (bx - 64) * 64; }
    gemm_body(A, DM, Bo, DFF, Cout, NGU, nullptr, m0, 2048);
}

// ---------------- split-K reduce (no residual; for qkv) ----------------
__global__ void __launch_bounds__(256) reduce_kernel(float* __restrict__ dst,
                                                     const float* __restrict__ part,
                                                     int total, int S) {
    int i = (blockIdx.x * 256 + threadIdx.x) * 4;
    if (i >= total) return;
    float4 v = make_float4(0.f, 0.f, 0.f, 0.f);
    for (int s = 0; s < S; s++) {
        float4 p = *(const float4*)(part + (size_t)s * total + i);
        v.x += p.x; v.y += p.y; v.z += p.z; v.w += p.w;
    }
    *(float4*)(dst + i) = v;
}

// ---------------- fused: hid += sum(part) ; hn = rmsnorm(hid, w) ----------
// one block per token row (DM=2048), S=4 partials, 256 threads.
__global__ void __launch_bounds__(256) reduce_norm_kernel(
    float* __restrict__ hid, const float* __restrict__ part,
    const float* __restrict__ w, float* __restrict__ hn) {
    int t = blockIdx.x;
    int tid = threadIdx.x;
    float4* hrow = (float4*)(hid + (size_t)t * DM);
    float4 v[2];
    float ss = 0.f;
#pragma unroll
    for (int j = 0; j < 2; j++) {
        int idx = tid + j * 256;           // float4 index within row (0..511)
        float4 a = hrow[idx];
#pragma unroll
        for (int s = 0; s < 4; s++) {
            float4 p = *(const float4*)(part + ((size_t)s * NT + t) * DM + idx * 4);
            a.x += p.x; a.y += p.y; a.z += p.z; a.w += p.w;
        }
        hrow[idx] = a;
        v[j] = a;
        ss += a.x*a.x + a.y*a.y + a.z*a.z + a.w*a.w;
    }
    __shared__ float red[8];
    for (int o = 16; o; o >>= 1) ss += __shfl_xor_sync(~0u, ss, o);
    if ((tid & 31) == 0) red[tid >> 5] = ss;
    __syncthreads();
    if (tid < 8) {
        float x = red[tid];
        for (int o = 4; o; o >>= 1) x += __shfl_xor_sync(0xff, x, o);
        if (tid == 0) red[0] = x;
    }
    __syncthreads();
    float inv = rsqrtf(red[0] / (float)DM + REPS);
    float4* nrow = (float4*)(hn + (size_t)t * DM);
#pragma unroll
    for (int j = 0; j < 2; j++) {
        int idx = tid + j * 256;
        float4 wv = *(const float4*)(w + idx * 4);
        float4 o;
        o.x = v[j].x * inv * wv.x;
        o.y = v[j].y * inv * wv.y;
        o.z = v[j].z * inv * wv.z;
        o.w = v[j].w * inv * wv.w;
        nrow[idx] = o;
    }
}

// ---------------- RoPE on fused qkv buffer ----------------
__global__ void rope_kernel(float* __restrict__ qkv) {
    int idx = blockIdx.x * blockDim.x + threadIdx.x;
    const int NQE = NT * NH  * 32;
    const int NKE = NT * NKV * 32;
    float* base; int d, pos;
    if (idx < NQE) {
        d = idx & 31;
        int h = (idx >> 5) % NH;
        int t = idx / (32 * NH);
        pos = NS + (t % NQ);
        base = qkv + (size_t)t * NQKV + h * HD;
    } else if (idx < NQE + NKE) {
        int j = idx - NQE;
        d = j & 31;
        int h = (j >> 5) % NKV;
        int t = j / (32 * NKV);
        pos = NS + (t % NQ);
        base = qkv + (size_t)t * NQKV + 2048 + h * HD;
    } else return;
    float inv = powf(10000.0f, -(float)d * (1.0f / 32.0f));
    float ang = (float)pos * inv;
    float c = cosf(ang), s = sinf(ang);
    float x1 = base[d], x2 = base[d + 32];
    base[d]      = x1 * c - x2 * s;
    base[d + 32] = x2 * c + x1 * s;
}

// ---------------- fused paged attention ----------------
__global__ void __launch_bounds__(256) attn_kernel(
    const float* __restrict__ kc, const float* __restrict__ vc,
    const int* __restrict__ page_table, const int* __restrict__ req_id,
    const float* __restrict__ qkv, float* __restrict__ aout) {

    __shared__ float q_s[16 * 64];
    __shared__ float sc [16 * 520];
    __shared__ float tile[64 * 33];
    __shared__ float rowinv[16];
    __shared__ int pages[NP];

    int kvh = blockIdx.x, b = blockIdx.y;
    int tid = threadIdx.x;

    if (tid < NP) pages[tid] = page_table[req_id[b] * NP + tid];
    {
        int row = tid >> 4;
        int d0  = (tid & 15) * 4;
        int hp = row >> 2, qi = row & 3;
        float4 v = *(const float4*)(qkv + (size_t)(b*NQ + qi) * NQKV + (kvh*4 + hp) * HD + d0);
        *(float4*)(q_s + row * 64 + d0) = v;
    }
    __syncthreads();

    const float scale = 0.125f;
    int jj_l = tid >> 3;
    int f4i  = tid & 7;
    int jj_c = tid & 31;
    int rgrp = tid >> 5;

    for (int t0 = 0; t0 < 16; t0++) {
        int j = t0 * 32 + jj_l;
        int page = pages[j >> 4];
        const float* kr = kc + (((size_t)page * PSZ + (j & 15)) * NKV + kvh) * HD;
#pragma unroll
        for (int i = 0; i < 2; i++) {
            int d0 = (f4i + 8 * i) * 4;
            float4 v = *(const float4*)(kr + d0);
            tile[(d0+0)*33 + jj_l] = v.x;
            tile[(d0+1)*33 + jj_l] = v.y;
            tile[(d0+2)*33 + jj_l] = v.z;
            tile[(d0+3)*33 + jj_l] = v.w;
        }
        __syncthreads();
        float a0 = 0.f, a1 = 0.f;
        const float* q0 = q_s + rgrp * 64;
        const float* q1 = q_s + (rgrp + 8) * 64;
#pragma unroll
        for (int d = 0; d < 64; d++) {
            float kv = tile[d * 33 + jj_c];
            a0 += kv * q0[d];
            a1 += kv * q1[d];
        }
        sc[rgrp       * 520 + t0*32 + jj_c] = a0 * scale;
        sc[(rgrp + 8) * 520 + t0*32 + jj_c] = a1 * scale;
        __syncthreads();
    }
    if (tid < 64) {
        int hp = tid >> 4, qi = (tid >> 2) & 3, qj = tid & 3;
        int row = hp * 4 + qi;
        const float* kr = qkv + (size_t)(b*NQ + qj) * NQKV + 2048 + kvh * HD;
        const float* qr = q_s + row * 64;
        float a = 0.f;
#pragma unroll
        for (int d = 0; d < 64; d++) a += qr[d] * kr[d];
        sc[row * 520 + 512 + qj] = (qj <= qi) ? a * scale : -1e30f;
    }
    __syncthreads();

    {
        int w = tid >> 5, lane = tid & 31;
        for (int rr = 0; rr < 2; rr++) {
            int row = w * 2 + rr;
            float* srow = sc + row * 520;
            float m = -1e30f;
            for (int j = lane; j < 516; j += 32) m = fmaxf(m, srow[j]);
            for (int o = 16; o; o >>= 1) m = fmaxf(m, __shfl_xor_sync(~0u, m, o));
            float s = 0.f;
            for (int j = lane; j < 516; j += 32) {
                float p = expf(srow[j] - m);
                srow[j] = p;
                s += p;
            }
            for (int o = 16; o; o >>= 1) s += __shfl_xor_sync(~0u, s, o);
            if (lane == 0) rowinv[row] = 1.f / s;
        }
    }
    __syncthreads();

    int d = tid & 63, rbase = tid >> 6;
    float oacc[4] = {0.f, 0.f, 0.f, 0.f};
    for (int t0 = 0; t0 < 16; t0++) {
        int j = t0 * 32 + jj_l;
        int page = pages[j >> 4];
        const float* vr = vc + (((size_t)page * PSZ + (j & 15)) * NKV + kvh) * HD;
#pragma unroll
        for (int i = 0; i < 2; i++) {
            int d0 = (f4i + 8 * i) * 4;
            float4 v = *(const float4*)(vr + d0);
            tile[(d0+0)*33 + jj_l] = v.x;
            tile[(d0+1)*33 + jj_l] = v.y;
            tile[(d0+2)*33 + jj_l] = v.z;
            tile[(d0+3)*33 + jj_l] = v.w;
        }
        __syncthreads();
#pragma unroll
        for (int jj = 0; jj < 32; jj++) {
            float vv = tile[d * 33 + jj];
            int jc = t0 * 32 + jj;
            oacc[0] += sc[(rbase     ) * 520 + jc] * vv;
            oacc[1] += sc[(rbase +  4) * 520 + jc] * vv;
            oacc[2] += sc[(rbase +  8) * 520 + jc] * vv;
            oacc[3] += sc[(rbase + 12) * 520 + jc] * vv;
        }
        __syncthreads();
    }
#pragma unroll
    for (int qj = 0; qj < 4; qj++) {
        float vv = qkv[(size_t)(b*NQ + qj) * NQKV + 2560 + kvh * HD + d];
        oacc[0] += sc[(rbase     ) * 520 + 512 + qj] * vv;
        oacc[1] += sc[(rbase +  4) * 520 + 512 + qj] * vv;
        oacc[2] += sc[(rbase +  8) * 520 + 512 + qj] * vv;
        oacc[3] += sc[(rbase + 12) * 520 + 512 + qj] * vv;
    }
#pragma unroll
    for (int r = 0; r < 4; r++) {
        int row = rbase + r * 4;
        int hp = row >> 2, qi = row & 3;
        aout[((size_t)(b*NQ + qi) * NH + (kvh*4 + hp)) * HD + d] = oacc[r] * rowinv[row];
    }
}

// ---------------- silu(gate) * up (in-place into gate region of gu) --------
__global__ void silu_mul_kernel(float* __restrict__ gu) {
    int i = blockIdx.x * blockDim.x + threadIdx.x;
    if (i < NT * DFF) {
        int row = i / DFF, c = i % DFF;
        float x = gu[(size_t)row * NGU + c];
        float u = gu[(size_t)row * NGU + DFF + c];
        gu[(size_t)row * NGU + c] = (x / (1.f + expf(-x))) * u;
    }
}

// ---------------- host orchestration ----------------
extern "C" void kernel_launch(void* const* d_in, const int* in_sizes, int n_in,
                              void* d_out, int out_size) {
    const int*   input_ids  = (const int*)  d_in[0];
    const int*   req_id     = (const int*)  d_in[1];
    const int*   page_table = (const int*)  d_in[2];
    const float* embed      = (const float*)d_in[3];
    const float* w_in_ln    = (const float*)d_in[4];
    const float* wq         = (const float*)d_in[5];
    const float* wk         = (const float*)d_in[6];
    const float* wv         = (const float*)d_in[7];
    const float* wo         = (const float*)d_in[8];
    const float* w_post_ln  = (const float*)d_in[9];
    const float* w_gate     = (const float*)d_in[10];
    const float* w_up       = (const float*)d_in[11];
    const float* w_down     = (const float*)d_in[12];
    const float* k_cache    = (const float*)d_in[13];
    const float* v_cache    = (const float*)d_in[14];
    const float* lm_head    = (const float*)d_in[15];
    float* out = (float*)d_out;

    float *hid, *hn, *qkvb, *ao, *gu, *part;
    cudaGetSymbolAddress((void**)&hid,  g_hidden);
    cudaGetSymbolAddress((void**)&hn,   g_hnorm);
    cudaGetSymbolAddress((void**)&qkvb, g_qkv);
    cudaGetSymbolAddress((void**)&ao,   g_attn);
    cudaGetSymbolAddress((void**)&gu,   g_gu);
    cudaGetSymbolAddress((void**)&part, g_part);

    embed_kernel<<<NT, 256>>>(embed, input_ids, hid);
    rmsnorm_kernel<<<NT, 256>>>(hid, w_in_ln, hn);   // layer 0 input norm

    for (int l = 0; l < NL; l++) {
        const float* wq_l = wq + (size_t)l * DM * (NH * HD);
        const float* wk_l = wk + (size_t)l * DM * (NKV * HD);
        const float* wv_l = wv + (size_t)l * DM * (NKV * HD);
        const float* wo_l = wo + (size_t)l * (NH * HD) * DM;
        const float* wg_l = w_gate + (size_t)l * DM * DFF;
        const float* wu_l = w_up   + (size_t)l * DM * DFF;
        const float* wd_l = w_down + (size_t)l * DFF * DM;
        const float* kc_l = k_cache + (size_t)l * NPAGES * PSZ * NKV * HD;
        const float* vc_l = v_cache + (size_t)l * NPAGES * PSZ * NKV * HD;
        // norm weight applied after the down-projection of THIS layer:
        const float* w_next = (l + 1 < NL) ? (w_in_ln + (size_t)(l + 1) * DM)
                                           : w_in_ln;   // dummy (hn unused after)

        gemm_qkv<<<dim3(48, 2, 4), 256>>>(hn, wq_l, wk_l, wv_l, part);
        reduce_kernel<<<(NT*NQKV)/1024, 256>>>(qkvb, part, NT*NQKV, 4);

        rope_kernel<<<(NT*NH*32 + NT*NKV*32) / 256, 256>>>(qkvb);
        attn_kernel<<<dim3(NKV, NB), 256>>>(kc_l, vc_l, page_table, req_id, qkvb, ao);

        gemm_k<<<dim3(32, 2, 4), 256>>>(ao, NH*HD, wo_l, part, nullptr, DM, 512);
        reduce_norm_kernel<<<NT, 256>>>(hid, part, w_post_ln + (size_t)l * DM, hn);

        gemm_gu<<<dim3(128, 2, 1), 256>>>(hn, wg_l, wu_l, gu);
        silu_mul_kernel<<<(NT * DFF + 255) / 256, 256>>>(gu);

        gemm_k<<<dim3(32, 2, 4), 256>>>(gu, NGU, wd_l, part, nullptr, DM, 1024);
        reduce_norm_kernel<<<NT, 256>>>(hid, part, w_next, hn);
    }

    gemm_k<<<dim3(NV/64, 2, 1), 256>>>(hid, DM, lm_head, out, nullptr, NV, 2048);
}